// round 14
// baseline (speedup 1.0000x reference)
#include <cuda_runtime.h>

// MeanConv: out = (1/7) * sum_{k in {3,5,7,9,11,13,15}} box_mean_k(x, replicate pad) * mask
//
// R11 = R10 resubmit (infra flake; same signature as R4, which passed on retry).
//  R7 + literal ring-slot addressing: r0 % 32 == 0 (SH=64), so every ring slot
//  index is a compile-time literal once the chunk loop is unrolled (outer cc x2,
//  inner c4 x4, cc*32 folded by hand). Consume LDS becomes base_reg + immediate.
//  Geometry, per-warp row ownership, register prefetch identical to R7.

#define H_DIM 4096
#define W_DIM 4096
#define TW    256
#define NTH   256
#define SH    64
#define HALO  7
#define NROWVALS (TW + 2*HALO)     // 270
#define TWP      272               // padded smem row stride (floats)
#define RING     32
#define CHUNK    8                 // rows per chunk == warps per block

__device__ __forceinline__ int clampi(int v, int lo, int hi) { return min(max(v, lo), hi); }

__global__ __launch_bounds__(NTH, 4)
void meanconv_kernel(const float* __restrict__ x,
                     const float* __restrict__ mask,
                     float* __restrict__ out)
{
    __shared__ float ring[RING][TWP];

    const int t    = threadIdx.x;
    const int lane = t & 31;
    const int wrp  = t >> 5;
    const int c0   = blockIdx.x * TW;
    const int r0   = blockIdx.y * SH;          // multiple of 64 -> r0 % 32 == 0
    const int j    = t + HALO;

    // ---- warp w loads global row (r0 + rel + w), clamped, into registers ----
    auto load_rows = [&](int rel, float (&pf)[9]) {
        const int grc = clampi(r0 + rel + wrp, 0, H_DIM - 1);
        const float* __restrict__ rowp = x + (size_t)grc * W_DIM;
        #pragma unroll
        for (int i = 0; i < 8; i++) {
            const int gc = clampi(c0 - HALO + lane + 32 * i, 0, W_DIM - 1);
            pf[i] = rowp[gc];
        }
        if (lane < NROWVALS - 256) {
            const int gc = clampi(c0 - HALO + lane + 256, 0, W_DIM - 1);
            pf[8] = rowp[gc];
        }
    };

    // ---- warp w: STS raw row into slot, warp-sync, in-place prefix scan ----
    // slot_base is a mod-32-reduced literal; +wrp is the only runtime part.
    auto commit_rows = [&](int slot_base, const float (&pf)[9]) {
        float* __restrict__ row = ring[(slot_base + wrp) & (RING - 1)];
        #pragma unroll
        for (int i = 0; i < 8; i++) row[lane + 32 * i] = pf[i];
        if (lane < NROWVALS - 256) row[lane + 256] = pf[8];
        __syncwarp();

        const int base = lane * 9;             // lanes 0..29 cover 0..269
        float ps[9];
        float tot = 0.0f;
        if (base < NROWVALS) {
            float s = row[base];
            ps[0] = s;
            #pragma unroll
            for (int i = 1; i < 9; i++) { s += row[base + i]; ps[i] = s; }
            tot = s;
        }
        float inc = tot;
        #pragma unroll
        for (int d = 1; d < 32; d <<= 1) {
            float n = __shfl_up_sync(0xffffffffu, inc, d);
            if (lane >= d) inc += n;
        }
        const float excl = inc - tot;
        __syncwarp();                          // raw reads done before overwrite
        if (lane == 0) row[0] = 0.0f;
        if (base < NROWVALS) {
            #pragma unroll
            for (int i = 0; i < 9; i++) row[base + i + 1] = excl + ps[i];
        }
    };

    float pf[9];

    // ---- preload rows rel -8..7 (slots 24..31, 0..7); prefetch rel 8..15 ----
    load_rows(-8, pf);  commit_rows(24, pf);   // (-8+32)&31 = 24
    load_rows(0,  pf);  commit_rows(0,  pf);
    load_rows(8,  pf);                         // chunk 0 raw rows -> registers
    __syncthreads();

    // ---- init vertical running sums: acc[ki] covers rel rows [-hk, hk] ----
    float acc[7];
    #pragma unroll
    for (int ki = 0; ki < 7; ki++) {
        const int hk = ki + 1;                 // k = 2*hk+1
        float a = 0.0f;
        #pragma unroll
        for (int d = -7; d <= 7; d++) {
            if (d < -hk || d > hk) continue;
            const float* __restrict__ rp = &ring[(d + 32) & 31][j];  // literal slot
            a += rp[hk + 1] - rp[-hk];
        }
        acc[ki] = a;
    }

    // ---- main sweep: slots depend only on (c4, rr, hk) -> all literals ----
    for (int cc = 0; cc < 2; cc++) {
        const int relcc = cc * 32;             // == 0 mod 32: dropped from slots

        #pragma unroll
        for (int c4 = 0; c4 < 4; c4++) {
            // produce: scanned rows rel (relcc + 8 + c4*8 + wrp)
            commit_rows((8 + c4 * 8) & 31, pf);
            if (!(cc == 1 && c4 == 3))
                load_rows(relcc + 16 + c4 * 8, pf);   // prefetch next chunk
            __syncthreads();

            const int crow = r0 + relcc + c4 * CHUNK;
            size_t idx = (size_t)crow * W_DIM + (size_t)(c0 + t);

            #pragma unroll
            for (int rr = 0; rr < CHUNK; rr++) {
                float s = acc[0] * (1.0f / (7.0f *   9.0f));
                s = fmaf(acc[1], 1.0f / (7.0f *  25.0f), s);
                s = fmaf(acc[2], 1.0f / (7.0f *  49.0f), s);
                s = fmaf(acc[3], 1.0f / (7.0f *  81.0f), s);
                s = fmaf(acc[4], 1.0f / (7.0f * 121.0f), s);
                s = fmaf(acc[5], 1.0f / (7.0f * 169.0f), s);
                s = fmaf(acc[6], 1.0f / (7.0f * 225.0f), s);
                __stcs(&out[idx], s * __ldcs(&mask[idx]));

                #pragma unroll
                for (int ki = 0; ki < 7; ki++) {
                    const int hk = ki + 1;
                    // literal slots: (c4*8 + rr +- off) & 31
                    const float* __restrict__ ra =
                        &ring[(c4 * 8 + rr + 1 + hk) & 31][j];
                    const float* __restrict__ rs =
                        &ring[(c4 * 8 + rr - hk + 32) & 31][j];
                    acc[ki] += (ra[hk + 1] - ra[-hk]) - (rs[hk + 1] - rs[-hk]);
                }
                idx += W_DIM;
            }
            // next commit writes slots (16 + c4*8 .. 23 + c4*8) & 31 — disjoint
            // from this chunk's read slots (c4*8 - 7 .. c4*8 + 15) & 31.
        }
    }
}

extern "C" void kernel_launch(void* const* d_in, const int* in_sizes, int n_in,
                              void* d_out, int out_size)
{
    const float* x    = (const float*)d_in[0];
    const float* mask = (const float*)d_in[1];
    float* out        = (float*)d_out;

    dim3 grid(W_DIM / TW, H_DIM / SH);
    dim3 block(NTH);
    meanconv_kernel<<<grid, block>>>(x, mask, out);
}